// round 4
// baseline (speedup 1.0000x reference)
#include <cuda_runtime.h>

#define TB 2
#define TT 1024
#define TH 8
#define TD 64
#define NLEV 11
#define NBH 16

// ---- scratch (no allocations allowed) ----
__device__ float d_Epos[NBH * TT];
__device__ float d_Eneg[NBH * TT];

// ---------------- scan kernel: E+/- = exp(+-cumsum g) per (b,h) ----------------
__global__ void hseg_scan_kernel(const float* __restrict__ g) {
    int bh = blockIdx.x;
    int b = bh >> 3, h = bh & 7;
    int t = threadIdx.x;                     // 0..1023
    float x = g[((size_t)(b * TT + t)) * TH + h];
    int lane = t & 31, wid = t >> 5;
    #pragma unroll
    for (int o = 1; o < 32; o <<= 1) {
        float y = __shfl_up_sync(0xffffffffu, x, o);
        if (lane >= o) x += y;
    }
    __shared__ float ws[32];
    if (lane == 31) ws[wid] = x;
    __syncthreads();
    if (wid == 0) {
        float s = ws[lane];
        #pragma unroll
        for (int o = 1; o < 32; o <<= 1) {
            float y = __shfl_up_sync(0xffffffffu, s, o);
            if (lane >= o) s += y;
        }
        ws[lane] = s;
    }
    __syncthreads();
    float tot = x + (wid ? ws[wid - 1] : 0.0f);
    d_Epos[bh * TT + t] = expf(tot);
    d_Eneg[bh * TT + t] = expf(-tot);
}

// ---------------- f32x2 helpers ----------------
typedef unsigned long long u64;
__device__ __forceinline__ u64 pk2(float lo, float hi) {
    u64 r; asm("mov.b64 %0,{%1,%2};" : "=l"(r) : "f"(lo), "f"(hi)); return r;
}
__device__ __forceinline__ float2 up2(u64 v) {
    float2 f; asm("mov.b64 {%0,%1},%2;" : "=f"(f.x), "=f"(f.y) : "l"(v)); return f;
}
__device__ __forceinline__ u64 ffma2(u64 a, u64 b, u64 c) {
    u64 d; asm("fma.rn.f32x2 %0,%1,%2,%3;" : "=l"(d) : "l"(a), "l"(b), "l"(c)); return d;
}

// smem layout (floats)
#define OFF_Q  0        // 64x64 d-major, swizzled groups
#define OFF_K  4096     // 64x64 d-major, swizzled groups
#define OFF_V  8192     // 64x64 j-major, plain
#define OFF_P  12288    // 64x66 (col-major P^T, pitch 66)
#define OFF_RF 16512    // 64x12 rowFac[i][lev]
#define OFF_EN 17280    // 64
#define SMEM_FLOATS 17344
#define SMEM_BYTES (SMEM_FLOATS * 4)

__global__ void __launch_bounds__(256, 2) hattn_kernel(
    const float* __restrict__ q, const float* __restrict__ k,
    const float* __restrict__ v, const float* __restrict__ Ls,
    float* __restrict__ out) {
    extern __shared__ float sm[];
    float* QsT = sm + OFF_Q;
    float* KsT = sm + OFF_K;
    float* Vs  = sm + OFF_V;
    float* PsT = sm + OFF_P;
    float* RF  = sm + OFF_RF;
    float* EN  = sm + OFF_EN;

    const int tid = threadIdx.x;
    const int tx = tid & 15, ty = tid >> 4;
    const int bh = blockIdx.x >> 4;
    const int b = bh >> 3, h = bh & 7;
    const int qt = 15 - (blockIdx.x & 15);   // heavy blocks first
    const int q0 = qt << 6;

    const float* qb = q + ((size_t)b * TT * TH + h) * TD;
    const float* kb = k + ((size_t)b * TT * TH + h) * TD;
    const float* vb = v + ((size_t)b * TT * TH + h) * TD;

    // ---- load Q tile, transposed (d-major) with XOR-swizzled column groups ----
    {
        int f4 = tid;
        #pragma unroll
        for (int rep = 0; rep < 4; rep++, f4 += 256) {
            int row = f4 >> 4;
            int dL  = f4 & 15;
            int dp  = dL << 2;
            float4 val = *reinterpret_cast<const float4*>(qb + (size_t)(q0 + row) * 512 + dp);
            int col = (((row >> 2) ^ dL) << 2) | (row & 3);
            QsT[(dp + 0) * 64 + col] = val.x;
            QsT[(dp + 1) * 64 + col] = val.y;
            QsT[(dp + 2) * 64 + col] = val.z;
            QsT[(dp + 3) * 64 + col] = val.w;
        }
    }
    // rowFac[i][lev] = L[b,h,lev,q0+i] * exp(G[q0+i])   (coalesced over i)
    for (int i = tid; i < 64 * NLEV; i += 256) {
        int r = i & 63, lev = i >> 6;
        RF[r * 12 + lev] = Ls[((size_t)bh * NLEV + lev) * TT + q0 + r] *
                           d_Epos[bh * TT + q0 + r];
    }

    u64 oacc[4][2];
    #pragma unroll
    for (int r = 0; r < 4; r++) { oacc[r][0] = 0ull; oacc[r][1] = 0ull; }

    for (int kt = 0; kt <= qt; kt++) {
        const int k0 = kt << 6;
        __syncthreads();   // protect KsT/Vs/PsT from prior-iteration readers

        // ---- load K (transposed+swizzled) and V (plain) tiles ----
        {
            int f4 = tid;
            #pragma unroll
            for (int rep = 0; rep < 4; rep++, f4 += 256) {
                int row = f4 >> 4;
                int dL  = f4 & 15;
                int dp  = dL << 2;
                const float4 kv = *reinterpret_cast<const float4*>(kb + (size_t)(k0 + row) * 512 + dp);
                const float4 vv = *reinterpret_cast<const float4*>(vb + (size_t)(k0 + row) * 512 + dp);
                int col = (((row >> 2) ^ dL) << 2) | (row & 3);
                KsT[(dp + 0) * 64 + col] = kv.x;
                KsT[(dp + 1) * 64 + col] = kv.y;
                KsT[(dp + 2) * 64 + col] = kv.z;
                KsT[(dp + 3) * 64 + col] = kv.w;
                *reinterpret_cast<float4*>(&Vs[row * 64 + dp]) = vv;
            }
        }
        if (tid < 64) EN[tid] = d_Eneg[bh * TT + k0 + tid];
        __syncthreads();

        // ---- GEMM1: S[i][j] = sum_d Q[i][d] * K[j][d]  (f32x2 over j-pairs) ----
        u64 s[4][2];
        #pragma unroll
        for (int r = 0; r < 4; r++) { s[r][0] = 0ull; s[r][1] = 0ull; }
        #pragma unroll 8
        for (int d = 0; d < 64; d++) {
            const int sw = (d >> 2) & 15;
            const float4 qv = *reinterpret_cast<const float4*>(&QsT[d * 64 + ((ty ^ sw) << 2)]);
            const float4 kv = *reinterpret_cast<const float4*>(&KsT[d * 64 + ((tx ^ sw) << 2)]);
            const u64 kp0 = pk2(kv.x, kv.y), kp1 = pk2(kv.z, kv.w);
            u64 a;
            a = pk2(qv.x, qv.x); s[0][0] = ffma2(a, kp0, s[0][0]); s[0][1] = ffma2(a, kp1, s[0][1]);
            a = pk2(qv.y, qv.y); s[1][0] = ffma2(a, kp0, s[1][0]); s[1][1] = ffma2(a, kp1, s[1][1]);
            a = pk2(qv.z, qv.z); s[2][0] = ffma2(a, kp0, s[2][0]); s[2][1] = ffma2(a, kp1, s[2][1]);
            a = pk2(qv.w, qv.w); s[3][0] = ffma2(a, kp0, s[3][0]); s[3][1] = ffma2(a, kp1, s[3][1]);
        }

        // ---- weighting: P = S * exp(G_i - G_j) * L[lev(i,j), i] ----
        float2 r0a = up2(s[0][0]), r0b = up2(s[0][1]);
        float2 r1a = up2(s[1][0]), r1b = up2(s[1][1]);
        float2 r2a = up2(s[2][0]), r2b = up2(s[2][1]);
        float2 r3a = up2(s[3][0]), r3b = up2(s[3][1]);
        float pv[4][4];
        pv[0][0] = r0a.x; pv[0][1] = r0a.y; pv[0][2] = r0b.x; pv[0][3] = r0b.y;
        pv[1][0] = r1a.x; pv[1][1] = r1a.y; pv[1][2] = r1b.x; pv[1][3] = r1b.y;
        pv[2][0] = r2a.x; pv[2][1] = r2a.y; pv[2][2] = r2b.x; pv[2][3] = r2b.y;
        pv[3][0] = r3a.x; pv[3][1] = r3a.y; pv[3][2] = r3b.x; pv[3][3] = r3b.y;

        float en[4];
        #pragma unroll
        for (int c = 0; c < 4; c++) en[c] = EN[4 * tx + c];

        float wv[4][4];
        if (kt != qt) {
            // level is CONSTANT across an off-diagonal 64x64 tile
            const int levc = 38 - __clz(qt ^ kt);   // 7 + msb(qt^kt)
            float wr[4];
            #pragma unroll
            for (int r = 0; r < 4; r++) wr[r] = RF[(4 * ty + r) * 12 + levc];
            #pragma unroll
            for (int r = 0; r < 4; r++)
                #pragma unroll
                for (int c = 0; c < 4; c++) wv[r][c] = wr[r] * en[c];
        } else {
            #pragma unroll
            for (int r = 0; r < 4; r++) {
                int il = 4 * ty + r;
                #pragma unroll
                for (int c = 0; c < 4; c++) {
                    int jl = 4 * tx + c;
                    int lev = 32 - __clz(il ^ jl);  // il==jl -> 0 (diagonal)
                    wv[r][c] = (jl <= il) ? RF[il * 12 + lev] * en[c] : 0.0f;
                }
            }
        }
        #pragma unroll
        for (int c = 0; c < 4; c++) {
            float* dst = &PsT[(4 * tx + c) * 66 + 4 * ty];
            *reinterpret_cast<float2*>(dst)     = make_float2(pv[0][c] * wv[0][c], pv[1][c] * wv[1][c]);
            *reinterpret_cast<float2*>(dst + 2) = make_float2(pv[2][c] * wv[2][c], pv[3][c] * wv[3][c]);
        }
        __syncthreads();

        // ---- GEMM2: O[i][d] += sum_j P[i][j] * V[j][d]  (f32x2 over d-pairs) ----
        #pragma unroll 8
        for (int j = 0; j < 64; j++) {
            float2 pA = *reinterpret_cast<const float2*>(&PsT[j * 66 + 4 * ty]);
            float2 pB = *reinterpret_cast<const float2*>(&PsT[j * 66 + 4 * ty + 2]);
            float4 vv = *reinterpret_cast<const float4*>(&Vs[j * 64 + 4 * tx]);
            const u64 vp0 = pk2(vv.x, vv.y), vp1 = pk2(vv.z, vv.w);
            u64 a;
            a = pk2(pA.x, pA.x); oacc[0][0] = ffma2(a, vp0, oacc[0][0]); oacc[0][1] = ffma2(a, vp1, oacc[0][1]);
            a = pk2(pA.y, pA.y); oacc[1][0] = ffma2(a, vp0, oacc[1][0]); oacc[1][1] = ffma2(a, vp1, oacc[1][1]);
            a = pk2(pB.x, pB.x); oacc[2][0] = ffma2(a, vp0, oacc[2][0]); oacc[2][1] = ffma2(a, vp1, oacc[2][1]);
            a = pk2(pB.y, pB.y); oacc[3][0] = ffma2(a, vp0, oacc[3][0]); oacc[3][1] = ffma2(a, vp1, oacc[3][1]);
        }
    }

    // ---- epilogue: out[b, q0+4ty+r, h, 4tx..4tx+3] ----
    #pragma unroll
    for (int r = 0; r < 4; r++) {
        float2 lo = up2(oacc[r][0]);
        float2 hi = up2(oacc[r][1]);
        size_t off = ((size_t)(b * TT + q0 + 4 * ty + r) * TH + h) * TD + 4 * tx;
        *reinterpret_cast<float4*>(out + off) = make_float4(lo.x, lo.y, hi.x, hi.y);
    }
}

extern "C" void kernel_launch(void* const* d_in, const int* in_sizes, int n_in,
                              void* d_out, int out_size) {
    const float* q  = (const float*)d_in[0];
    const float* k  = (const float*)d_in[1];
    const float* v  = (const float*)d_in[2];
    const float* g  = (const float*)d_in[3];
    const float* ls = (const float*)d_in[4];
    float* out = (float*)d_out;

    cudaFuncSetAttribute(hattn_kernel, cudaFuncAttributeMaxDynamicSharedMemorySize,
                         SMEM_BYTES);

    hseg_scan_kernel<<<NBH, TT>>>(g);
    hattn_kernel<<<256, 256, SMEM_BYTES>>>(q, k, v, ls, out);
}

// round 6
// speedup vs baseline: 1.5695x; 1.5695x over previous
#include <cuda_runtime.h>

#define TB 2
#define TT 1024
#define TH 8
#define TD 64
#define NLEV 11
#define NBH 16

// ---- scratch (no allocations allowed) ----
__device__ float d_Epos[NBH * TT];
__device__ float d_Eneg[NBH * TT];

// ---------------- scan kernel: E+/- = exp(+-cumsum g) per (b,h) ----------------
__global__ void hseg_scan_kernel(const float* __restrict__ g) {
    int bh = blockIdx.x;
    int b = bh >> 3, h = bh & 7;
    int t = threadIdx.x;                     // 0..1023
    float x = g[((size_t)(b * TT + t)) * TH + h];
    int lane = t & 31, wid = t >> 5;
    #pragma unroll
    for (int o = 1; o < 32; o <<= 1) {
        float y = __shfl_up_sync(0xffffffffu, x, o);
        if (lane >= o) x += y;
    }
    __shared__ float ws[32];
    if (lane == 31) ws[wid] = x;
    __syncthreads();
    if (wid == 0) {
        float s = ws[lane];
        #pragma unroll
        for (int o = 1; o < 32; o <<= 1) {
            float y = __shfl_up_sync(0xffffffffu, s, o);
            if (lane >= o) s += y;
        }
        ws[lane] = s;
    }
    __syncthreads();
    float tot = x + (wid ? ws[wid - 1] : 0.0f);
    d_Epos[bh * TT + t] = expf(tot);
    d_Eneg[bh * TT + t] = expf(-tot);
}

// ---------------- f32x2 helpers ----------------
typedef unsigned long long u64;
__device__ __forceinline__ u64 pk2(float lo, float hi) {
    u64 r; asm("mov.b64 %0,{%1,%2};" : "=l"(r) : "f"(lo), "f"(hi)); return r;
}
__device__ __forceinline__ float2 up2(u64 v) {
    float2 f; asm("mov.b64 {%0,%1},%2;" : "=f"(f.x), "=f"(f.y) : "l"(v)); return f;
}
__device__ __forceinline__ u64 ffma2(u64 a, u64 b, u64 c) {
    u64 d; asm("fma.rn.f32x2 %0,%1,%2,%3;" : "=l"(d) : "l"(a), "l"(b), "l"(c)); return d;
}

// smem layout (floats)
#define OFF_Q  0        // 64x64 d-major, swizzled groups
#define OFF_K  4096     // 64x64 d-major, swizzled groups
#define OFF_V  8192     // 64x64 j-major, plain
#define OFF_P  12288    // 64x66 (col-major P^T, pitch 66)
#define OFF_RF 16512    // 64x12 rowFac[i][lev]
#define OFF_EN 17280    // 64
#define SMEM_FLOATS 17344
#define SMEM_BYTES (SMEM_FLOATS * 4)

__global__ void __launch_bounds__(256, 2) hattn_kernel(
    const float* __restrict__ q, const float* __restrict__ k,
    const float* __restrict__ v, const float* __restrict__ Ls,
    float* __restrict__ out) {
    extern __shared__ float sm[];
    float* QsT = sm + OFF_Q;
    float* KsT = sm + OFF_K;
    float* Vs  = sm + OFF_V;
    float* PsT = sm + OFF_P;
    float* RF  = sm + OFF_RF;
    float* EN  = sm + OFF_EN;

    const int tid = threadIdx.x;
    const int tx = tid & 15, ty = tid >> 4;
    const int bh = blockIdx.x >> 4;
    const int b = bh >> 3, h = bh & 7;
    const int idx = blockIdx.x & 15;
    const int p = idx >> 1;          // pair index 0..7
    const int s = idx & 1;
    const int at = p, bt = 15 - p;   // pair (at, bt): work (at+1) + (16-at) = 17

    // segment schedule: s=0 -> {qt=bt, kt in [0,8)}           (8 tiles, atomic)
    //                   s=1 -> {qt=bt, kt in [8,bt]} (atomic) + {qt=at, all kt} (store)
    int segQt[2], segLo[2], segHi[2], segAt[2], nseg;
    if (s == 0) {
        nseg = 1;
        segQt[0] = bt; segLo[0] = 0; segHi[0] = 8;      segAt[0] = 1;
    } else {
        nseg = 2;
        segQt[0] = bt; segLo[0] = 8; segHi[0] = bt + 1; segAt[0] = 1;
        segQt[1] = at; segLo[1] = 0; segHi[1] = at + 1; segAt[1] = 0;
    }

    const float* qb = q + ((size_t)b * TT * TH + h) * TD;
    const float* kb = k + ((size_t)b * TT * TH + h) * TD;
    const float* vb = v + ((size_t)b * TT * TH + h) * TD;

    for (int sg = 0; sg < nseg; sg++) {
        const int qt = segQt[sg];
        const int q0 = qt << 6;

        // ---- load Q tile, transposed (d-major) with XOR-swizzled column groups ----
        {
            int f4 = tid;
            #pragma unroll
            for (int rep = 0; rep < 4; rep++, f4 += 256) {
                int row = f4 >> 4;
                int dL  = f4 & 15;
                int dp  = dL << 2;
                float4 val = *reinterpret_cast<const float4*>(qb + (size_t)(q0 + row) * 512 + dp);
                int col = (((row >> 2) ^ dL) << 2) | (row & 3);
                QsT[(dp + 0) * 64 + col] = val.x;
                QsT[(dp + 1) * 64 + col] = val.y;
                QsT[(dp + 2) * 64 + col] = val.z;
                QsT[(dp + 3) * 64 + col] = val.w;
            }
        }
        // rowFac[i][lev] = L[b,h,lev,q0+i] * exp(G[q0+i])   (coalesced over i)
        for (int i = tid; i < 64 * NLEV; i += 256) {
            int r = i & 63, lev = i >> 6;
            RF[r * 12 + lev] = Ls[((size_t)bh * NLEV + lev) * TT + q0 + r] *
                               d_Epos[bh * TT + q0 + r];
        }

        u64 oacc[4][2];
        #pragma unroll
        for (int r = 0; r < 4; r++) { oacc[r][0] = 0ull; oacc[r][1] = 0ull; }

        for (int kt = segLo[sg]; kt < segHi[sg]; kt++) {
            const int k0 = kt << 6;
            __syncthreads();   // protect KsT/Vs/EN/PsT from prior-iteration readers

            // ---- load K (transposed+swizzled) and V (plain) tiles ----
            {
                int f4 = tid;
                #pragma unroll
                for (int rep = 0; rep < 4; rep++, f4 += 256) {
                    int row = f4 >> 4;
                    int dL  = f4 & 15;
                    int dp  = dL << 2;
                    const float4 kv = *reinterpret_cast<const float4*>(kb + (size_t)(k0 + row) * 512 + dp);
                    const float4 vv = *reinterpret_cast<const float4*>(vb + (size_t)(k0 + row) * 512 + dp);
                    int col = (((row >> 2) ^ dL) << 2) | (row & 3);
                    KsT[(dp + 0) * 64 + col] = kv.x;
                    KsT[(dp + 1) * 64 + col] = kv.y;
                    KsT[(dp + 2) * 64 + col] = kv.z;
                    KsT[(dp + 3) * 64 + col] = kv.w;
                    *reinterpret_cast<float4*>(&Vs[row * 64 + dp]) = vv;
                }
            }
            if (tid < 64) EN[tid] = d_Eneg[bh * TT + k0 + tid];
            __syncthreads();

            // ---- GEMM1: S[i][j] = sum_d Q[i][d] * K[j][d]  (f32x2 over j-pairs) ----
            u64 sa[4][2];
            #pragma unroll
            for (int r = 0; r < 4; r++) { sa[r][0] = 0ull; sa[r][1] = 0ull; }
            #pragma unroll 8
            for (int d = 0; d < 64; d++) {
                const int sw = (d >> 2) & 15;
                const float4 qv = *reinterpret_cast<const float4*>(&QsT[d * 64 + ((ty ^ sw) << 2)]);
                const ulonglong2 kp = *reinterpret_cast<const ulonglong2*>(&KsT[d * 64 + ((tx ^ sw) << 2)]);
                u64 a;
                a = pk2(qv.x, qv.x); sa[0][0] = ffma2(a, kp.x, sa[0][0]); sa[0][1] = ffma2(a, kp.y, sa[0][1]);
                a = pk2(qv.y, qv.y); sa[1][0] = ffma2(a, kp.x, sa[1][0]); sa[1][1] = ffma2(a, kp.y, sa[1][1]);
                a = pk2(qv.z, qv.z); sa[2][0] = ffma2(a, kp.x, sa[2][0]); sa[2][1] = ffma2(a, kp.y, sa[2][1]);
                a = pk2(qv.w, qv.w); sa[3][0] = ffma2(a, kp.x, sa[3][0]); sa[3][1] = ffma2(a, kp.y, sa[3][1]);
            }

            // ---- weighting: P = S * exp(G_i - G_j) * L[lev(i,j), i] ----
            float pv[4][4];
            #pragma unroll
            for (int r = 0; r < 4; r++) {
                float2 lo = up2(sa[r][0]), hi = up2(sa[r][1]);
                pv[r][0] = lo.x; pv[r][1] = lo.y; pv[r][2] = hi.x; pv[r][3] = hi.y;
            }

            float en[4];
            #pragma unroll
            for (int c = 0; c < 4; c++) en[c] = EN[4 * tx + c];

            float wv[4][4];
            if (kt != qt) {
                // level is CONSTANT across an off-diagonal 64x64 tile
                const int levc = 38 - __clz(qt ^ kt);   // 7 + msb(qt^kt)
                float wr[4];
                #pragma unroll
                for (int r = 0; r < 4; r++) wr[r] = RF[(4 * ty + r) * 12 + levc];
                #pragma unroll
                for (int r = 0; r < 4; r++)
                    #pragma unroll
                    for (int c = 0; c < 4; c++) wv[r][c] = wr[r] * en[c];
            } else {
                #pragma unroll
                for (int r = 0; r < 4; r++) {
                    int il = 4 * ty + r;
                    #pragma unroll
                    for (int c = 0; c < 4; c++) {
                        int jl = 4 * tx + c;
                        int lev = 32 - __clz(il ^ jl);  // il==jl -> 0 (diagonal)
                        wv[r][c] = (jl <= il) ? RF[il * 12 + lev] * en[c] : 0.0f;
                    }
                }
            }
            #pragma unroll
            for (int c = 0; c < 4; c++) {
                float* dst = &PsT[(4 * tx + c) * 66 + 4 * ty];
                *reinterpret_cast<float2*>(dst)     = make_float2(pv[0][c] * wv[0][c], pv[1][c] * wv[1][c]);
                *reinterpret_cast<float2*>(dst + 2) = make_float2(pv[2][c] * wv[2][c], pv[3][c] * wv[3][c]);
            }
            __syncthreads();

            // ---- GEMM2: O[i][d] += sum_j P[i][j] * V[j][d]  (f32x2 over d-pairs) ----
            #pragma unroll 8
            for (int j = 0; j < 64; j++) {
                float2 pA = *reinterpret_cast<const float2*>(&PsT[j * 66 + 4 * ty]);
                float2 pB = *reinterpret_cast<const float2*>(&PsT[j * 66 + 4 * ty + 2]);
                const ulonglong2 vp = *reinterpret_cast<const ulonglong2*>(&Vs[j * 64 + 4 * tx]);
                u64 a;
                a = pk2(pA.x, pA.x); oacc[0][0] = ffma2(a, vp.x, oacc[0][0]); oacc[0][1] = ffma2(a, vp.y, oacc[0][1]);
                a = pk2(pA.y, pA.y); oacc[1][0] = ffma2(a, vp.x, oacc[1][0]); oacc[1][1] = ffma2(a, vp.y, oacc[1][1]);
                a = pk2(pB.x, pB.x); oacc[2][0] = ffma2(a, vp.x, oacc[2][0]); oacc[2][1] = ffma2(a, vp.y, oacc[2][1]);
                a = pk2(pB.y, pB.y); oacc[3][0] = ffma2(a, vp.x, oacc[3][0]); oacc[3][1] = ffma2(a, vp.y, oacc[3][1]);
            }
        }

        // ---- epilogue: out[b, q0+4ty+r, h, 4tx..4tx+3] ----
        if (segAt[sg]) {
            #pragma unroll
            for (int r = 0; r < 4; r++) {
                float2 lo = up2(oacc[r][0]);
                float2 hi = up2(oacc[r][1]);
                float* dst = out + ((size_t)(b * TT + q0 + 4 * ty + r) * TH + h) * TD + 4 * tx;
                atomicAdd(dst + 0, lo.x);
                atomicAdd(dst + 1, lo.y);
                atomicAdd(dst + 2, hi.x);
                atomicAdd(dst + 3, hi.y);
            }
        } else {
            #pragma unroll
            for (int r = 0; r < 4; r++) {
                float2 lo = up2(oacc[r][0]);
                float2 hi = up2(oacc[r][1]);
                size_t off = ((size_t)(b * TT + q0 + 4 * ty + r) * TH + h) * TD + 4 * tx;
                *reinterpret_cast<float4*>(out + off) = make_float4(lo.x, lo.y, hi.x, hi.y);
            }
        }
        __syncthreads();   // QsT/RF rewrite protection for next segment
    }
}

extern "C" void kernel_launch(void* const* d_in, const int* in_sizes, int n_in,
                              void* d_out, int out_size) {
    const float* q  = (const float*)d_in[0];
    const float* k  = (const float*)d_in[1];
    const float* v  = (const float*)d_in[2];
    const float* g  = (const float*)d_in[3];
    const float* ls = (const float*)d_in[4];
    float* out = (float*)d_out;

    cudaFuncSetAttribute(hattn_kernel, cudaFuncAttributeMaxDynamicSharedMemorySize,
                         SMEM_BYTES);

    cudaMemsetAsync(out, 0, (size_t)out_size * sizeof(float));
    hseg_scan_kernel<<<NBH, TT>>>(g);
    hattn_kernel<<<256, 256, SMEM_BYTES>>>(q, k, v, ls, out);
}